// round 1
// baseline (speedup 1.0000x reference)
#include <cuda_runtime.h>
#include <cuda_bf16.h>
#include <math.h>

#define NN 4096
#define EE 65536
// hidden dims: 2H = 256, H = 128

// ------------------- scratch (static device globals; no allocs) -------------
__device__ float g_P[NN * 512];    // [x@Wl | x@Wr]
__device__ float g_A[NN * 256];    // aggregation scratch (256-dim)
__device__ float g_B[NN * 256];    // h buffers
__device__ float g_C[NN * 256];
__device__ float g_D[NN * 128];
__device__ float g_E[NN * 128];
__device__ int   g_cnt[NN];        // in-degree (dst counts, no self loop)
__device__ float g_dinv[NN];       // (deg+1)^-1/2  for GCN (with self loops)

// ------------------------------- utility kernels ----------------------------
__global__ void k_zero_cnt() {
    int i = blockIdx.x * blockDim.x + threadIdx.x;
    if (i < NN) g_cnt[i] = 0;
}

__global__ void k_count(const int* __restrict__ dst) {
    int e = blockIdx.x * blockDim.x + threadIdx.x;
    if (e < EE) atomicAdd(&g_cnt[dst[e]], 1);
}

__global__ void k_dinv() {
    int i = blockIdx.x * blockDim.x + threadIdx.x;
    if (i < NN) g_dinv[i] = rsqrtf((float)(g_cnt[i] + 1));
}

__global__ void k_zero_f(float* __restrict__ p, int n) {
    int i = blockIdx.x * blockDim.x + threadIdx.x;
    if (i < n) p[i] = 0.0f;
}

// SAGE: scatter-add P_l[src] into g_A[dst]  (256 floats / edge, float4 lanes)
__global__ void k_sage_agg(const int* __restrict__ src, const int* __restrict__ dst) {
    int t = blockIdx.x * blockDim.x + threadIdx.x;
    if (t >= EE * 64) return;
    int e = t >> 6;
    int q = t & 63;
    int s = src[e];
    int d = dst[e];
    float4 v = ((const float4*)(g_P + (size_t)s * 512))[q];
    float* out = g_A + (size_t)d * 256 + q * 4;
    atomicAdd(out + 0, v.x);
    atomicAdd(out + 1, v.y);
    atomicAdd(out + 2, v.z);
    atomicAdd(out + 3, v.w);
}

// h1 = relu(agg/max(deg,1) + bl + P_r)
__global__ void k_sage_combine(const float* __restrict__ bl) {
    int i = blockIdx.x * blockDim.x + threadIdx.x;
    if (i >= NN * 256) return;
    int v = i >> 8;
    int c = i & 255;
    float inv = 1.0f / fmaxf((float)g_cnt[v], 1.0f);
    float val = g_A[i] * inv + bl[c] + g_P[(size_t)v * 512 + 256 + c];
    g_B[i] = fmaxf(val, 0.0f);
}

// GCN: init agg with self-loop term dinv[v]^2 * hw[v]
__global__ void k_gcn_init(const float* __restrict__ hw, float* __restrict__ agg, int H) {
    int i = blockIdx.x * blockDim.x + threadIdx.x;
    if (i >= NN * H) return;
    int v = i / H;
    float dv = g_dinv[v];
    agg[i] = dv * dv * hw[i];
}

// GCN: agg[dst] += dinv[s]*dinv[d] * hw[src]
__global__ void k_gcn_agg(const int* __restrict__ src, const int* __restrict__ dst,
                          const float* __restrict__ hw, float* __restrict__ agg, int Hq) {
    int t = blockIdx.x * blockDim.x + threadIdx.x;
    if (t >= EE * Hq) return;
    int e = t / Hq;
    int q = t - e * Hq;
    int s = src[e];
    int d = dst[e];
    float norm = g_dinv[s] * g_dinv[d];
    int H = Hq * 4;
    float4 v = ((const float4*)(hw + (size_t)s * H))[q];
    float* out = agg + (size_t)d * H + q * 4;
    atomicAdd(out + 0, norm * v.x);
    atomicAdd(out + 1, norm * v.y);
    atomicAdd(out + 2, norm * v.z);
    atomicAdd(out + 3, norm * v.w);
}

__global__ void k_bias_relu(const float* __restrict__ in, const float* __restrict__ b,
                            float* __restrict__ out, int H) {
    int i = blockIdx.x * blockDim.x + threadIdx.x;
    if (i >= NN * H) return;
    int c = i % H;
    out[i] = fmaxf(in[i] + b[c], 0.0f);
}

// -------------------------------- SGEMM --------------------------------------
// C[M,N] = A[M,K] @ B[K,N] (+bias)(+relu), all row-major.
// Dual-B: for column tiles with col0 >= nsplit, read from B2 at col0-nsplit
// (used to compute x @ [Wl | Wr] in one launch). BN=128 divides nsplit=256.
// Tiles: BM=64, BN=128, BK=16; 256 threads; 4x8 micro-tile per thread.
__global__ void __launch_bounds__(256)
sgemm(int M, int N, int K,
      const float* __restrict__ A, int lda,
      const float* __restrict__ B, int ldb,
      const float* __restrict__ B2, int nsplit,
      float* __restrict__ C, int ldc,
      const float* __restrict__ bias, int do_relu)
{
    const int BM = 64, BN = 128, BK = 16;
    __shared__ float As[BK][BM];
    __shared__ float Bs[BK][BN];

    int tid = threadIdx.x;
    int tx = tid & 15;   // 16 col-groups * 8 cols
    int ty = tid >> 4;   // 16 row-groups * 4 rows
    int row0 = blockIdx.y * BM;
    int col0 = blockIdx.x * BN;

    const float* Bp = B;
    int cb = col0;
    if (col0 >= nsplit) { Bp = B2; cb = col0 - nsplit; }

    float acc[4][8];
    #pragma unroll
    for (int i = 0; i < 4; i++)
        #pragma unroll
        for (int j = 0; j < 8; j++) acc[i][j] = 0.0f;

    for (int k0 = 0; k0 < K; k0 += BK) {
        // load A tile: 64x16 = 256 float4, one per thread, store transposed
        {
            int m  = tid >> 2;            // 0..63
            int kk = (tid & 3) << 2;      // 0,4,8,12
            float4 v = *(const float4*)&A[(size_t)(row0 + m) * lda + k0 + kk];
            As[kk + 0][m] = v.x;
            As[kk + 1][m] = v.y;
            As[kk + 2][m] = v.z;
            As[kk + 3][m] = v.w;
        }
        // load B tile: 16x128 = 512 float4, two per thread
        #pragma unroll
        for (int l = 0; l < 2; l++) {
            int i = tid + l * 256;
            int k = i >> 5;               // 0..15
            int n = (i & 31) << 2;        // 0..124
            *(float4*)&Bs[k][n] = *(const float4*)&Bp[(size_t)(k0 + k) * ldb + cb + n];
        }
        __syncthreads();

        #pragma unroll
        for (int k = 0; k < BK; k++) {
            float a[4], b[8];
            *(float4*)&a[0] = *(float4*)&As[k][ty * 4];
            *(float4*)&b[0] = *(float4*)&Bs[k][tx * 8];
            *(float4*)&b[4] = *(float4*)&Bs[k][tx * 8 + 4];
            #pragma unroll
            for (int i = 0; i < 4; i++)
                #pragma unroll
                for (int j = 0; j < 8; j++)
                    acc[i][j] = fmaf(a[i], b[j], acc[i][j]);
        }
        __syncthreads();
    }

    #pragma unroll
    for (int i = 0; i < 4; i++) {
        int gm = row0 + ty * 4 + i;
        #pragma unroll
        for (int j = 0; j < 8; j += 4) {
            int gn = col0 + tx * 8 + j;
            float4 v;
            v.x = acc[i][j + 0];
            v.y = acc[i][j + 1];
            v.z = acc[i][j + 2];
            v.w = acc[i][j + 3];
            if (bias) {
                v.x += bias[gn + 0];
                v.y += bias[gn + 1];
                v.z += bias[gn + 2];
                v.w += bias[gn + 3];
            }
            if (do_relu) {
                v.x = fmaxf(v.x, 0.0f);
                v.y = fmaxf(v.y, 0.0f);
                v.z = fmaxf(v.z, 0.0f);
                v.w = fmaxf(v.w, 0.0f);
            }
            *(float4*)&C[(size_t)gm * ldc + gn] = v;
        }
    }
}

// ------------------------------ host orchestration ---------------------------
static void launch_gemm(int M, int N, int K,
                        const float* A, int lda,
                        const float* B, int ldb,
                        const float* B2, int nsplit,
                        float* C, int ldc,
                        const float* bias, int do_relu)
{
    dim3 grid(N / 128, M / 64);
    sgemm<<<grid, 256>>>(M, N, K, A, lda, B, ldb, B2, nsplit, C, ldc, bias, do_relu);
}

extern "C" void kernel_launch(void* const* d_in, const int* in_sizes, int n_in,
                              void* d_out, int out_size)
{
    const float* x       = (const float*)d_in[0];
    const int*   eidx    = (const int*)  d_in[1];
    const float* sage_Wl = (const float*)d_in[2];
    const float* sage_bl = (const float*)d_in[3];
    const float* sage_Wr = (const float*)d_in[4];
    const float* gcn1_W  = (const float*)d_in[5];
    const float* gcn1_b  = (const float*)d_in[6];
    const float* gcn2_W  = (const float*)d_in[7];
    const float* gcn2_b  = (const float*)d_in[8];
    const float* fc1_W   = (const float*)d_in[9];
    const float* fc1_b   = (const float*)d_in[10];
    const float* fc2_W   = (const float*)d_in[11];
    const float* fc2_b   = (const float*)d_in[12];
    const float* out_W   = (const float*)d_in[13];
    const float* out_b   = (const float*)d_in[14];
    float* out = (float*)d_out;

    const int* src = eidx;        // edge_index[0]
    const int* dst = eidx + EE;   // edge_index[1]

    float *P, *A, *B, *C, *D, *E;
    cudaGetSymbolAddress((void**)&P, g_P);
    cudaGetSymbolAddress((void**)&A, g_A);
    cudaGetSymbolAddress((void**)&B, g_B);
    cudaGetSymbolAddress((void**)&C, g_C);
    cudaGetSymbolAddress((void**)&D, g_D);
    cudaGetSymbolAddress((void**)&E, g_E);

    const int TPB = 256;

    // degrees (shared by SAGE mean and both GCN layers)
    k_zero_cnt<<<(NN + TPB - 1) / TPB, TPB>>>();
    k_count<<<(EE + TPB - 1) / TPB, TPB>>>(dst);
    k_dinv<<<(NN + TPB - 1) / TPB, TPB>>>();

    // P = x @ [Wl | Wr]   (4096 x 4096 x 512)
    launch_gemm(NN, 512, NN, x, NN, sage_Wl, 256, sage_Wr, 256, P, 512, nullptr, 0);

    // SAGE: mean-aggregate P_l over edges, combine with P_r + bias, relu -> g_B
    k_zero_f<<<(NN * 256 + TPB - 1) / TPB, TPB>>>(A, NN * 256);
    k_sage_agg<<<(EE * 64 + TPB - 1) / TPB, TPB>>>(src, dst);
    k_sage_combine<<<(NN * 256 + TPB - 1) / TPB, TPB>>>(sage_bl);

    // GCN1: hw = h1 @ W  (4096 x 256 x 256), agg with sym-norm + self loops
    launch_gemm(NN, 256, 256, B, 256, gcn1_W, 256, gcn1_W, 256, C, 256, nullptr, 0);
    k_gcn_init<<<(NN * 256 + TPB - 1) / TPB, TPB>>>(C, A, 256);
    k_gcn_agg<<<(EE * 64 + TPB - 1) / TPB, TPB>>>(src, dst, C, A, 64);
    k_bias_relu<<<(NN * 256 + TPB - 1) / TPB, TPB>>>(A, gcn1_b, B, 256);

    // GCN2: 256 -> 128
    launch_gemm(NN, 128, 256, B, 256, gcn2_W, 128, gcn2_W, 128, D, 128, nullptr, 0);
    k_gcn_init<<<(NN * 128 + TPB - 1) / TPB, TPB>>>(D, E, 128);
    k_gcn_agg<<<(EE * 32 + TPB - 1) / TPB, TPB>>>(src, dst, D, E, 32);
    k_bias_relu<<<(NN * 128 + TPB - 1) / TPB, TPB>>>(E, gcn2_b, D, 128);

    // fc1: D -> E, fc2: E -> C (reusing g_C low half)
    launch_gemm(NN, 128, 128, D, 128, fc1_W, 128, fc1_W, 128, E, 128, fc1_b, 1);
    launch_gemm(NN, 128, 128, E, 128, fc2_W, 128, fc2_W, 128, C, 128, fc2_b, 1);

    // output head: logits = h5 @ out_W + out_b  (4096 x 128 x 16384)
    launch_gemm(NN, 16384, 128, C, 128, out_W, 16384, out_W, 16384, out, 16384, out_b, 0);
}

// round 2
// speedup vs baseline: 1.3960x; 1.3960x over previous
#include <cuda_runtime.h>
#include <cuda_bf16.h>
#include <math.h>

#define NN 4096
#define EE 65536
// hidden dims: 2H = 256, H = 128

// ------------------- scratch (static device globals; no allocs) -------------
__device__ float g_P[NN * 512];    // [x@Wl | x@Wr]
__device__ float g_A[NN * 256];    // aggregation scratch (256-dim)
__device__ float g_B[NN * 256];    // h buffers
__device__ float g_C[NN * 256];
__device__ float g_D[NN * 128];
__device__ float g_E[NN * 128];
__device__ int   g_cnt[NN];        // in-degree (dst counts, no self loop)
__device__ float g_dinv[NN];       // (deg+1)^-1/2  for GCN (with self loops)

// ------------------------------- utility kernels ----------------------------
__global__ void k_zero_cnt() {
    int i = blockIdx.x * blockDim.x + threadIdx.x;
    if (i < NN) g_cnt[i] = 0;
}

__global__ void k_count(const int* __restrict__ dst) {
    int e = blockIdx.x * blockDim.x + threadIdx.x;
    if (e < EE) atomicAdd(&g_cnt[dst[e]], 1);
}

__global__ void k_dinv() {
    int i = blockIdx.x * blockDim.x + threadIdx.x;
    if (i < NN) g_dinv[i] = rsqrtf((float)(g_cnt[i] + 1));
}

__global__ void k_zero_f(float* __restrict__ p, int n) {
    int i = blockIdx.x * blockDim.x + threadIdx.x;
    if (i < n) p[i] = 0.0f;
}

// SAGE: scatter-add P_l[src] into g_A[dst]  (256 floats / edge, float4 lanes)
__global__ void k_sage_agg(const int* __restrict__ src, const int* __restrict__ dst) {
    int t = blockIdx.x * blockDim.x + threadIdx.x;
    if (t >= EE * 64) return;
    int e = t >> 6;
    int q = t & 63;
    int s = src[e];
    int d = dst[e];
    float4 v = ((const float4*)(g_P + (size_t)s * 512))[q];
    float* out = g_A + (size_t)d * 256 + q * 4;
    atomicAdd(out + 0, v.x);
    atomicAdd(out + 1, v.y);
    atomicAdd(out + 2, v.z);
    atomicAdd(out + 3, v.w);
}

// h1 = relu(agg/max(deg,1) + bl + P_r)
__global__ void k_sage_combine(const float* __restrict__ bl) {
    int i = blockIdx.x * blockDim.x + threadIdx.x;
    if (i >= NN * 256) return;
    int v = i >> 8;
    int c = i & 255;
    float inv = 1.0f / fmaxf((float)g_cnt[v], 1.0f);
    float val = g_A[i] * inv + bl[c] + g_P[(size_t)v * 512 + 256 + c];
    g_B[i] = fmaxf(val, 0.0f);
}

// GCN: init agg with self-loop term dinv[v]^2 * hw[v]
__global__ void k_gcn_init(const float* __restrict__ hw, float* __restrict__ agg, int H) {
    int i = blockIdx.x * blockDim.x + threadIdx.x;
    if (i >= NN * H) return;
    int v = i / H;
    float dv = g_dinv[v];
    agg[i] = dv * dv * hw[i];
}

// GCN: agg[dst] += dinv[s]*dinv[d] * hw[src]
__global__ void k_gcn_agg(const int* __restrict__ src, const int* __restrict__ dst,
                          const float* __restrict__ hw, float* __restrict__ agg, int Hq) {
    int t = blockIdx.x * blockDim.x + threadIdx.x;
    if (t >= EE * Hq) return;
    int e = t / Hq;
    int q = t - e * Hq;
    int s = src[e];
    int d = dst[e];
    float norm = g_dinv[s] * g_dinv[d];
    int H = Hq * 4;
    float4 v = ((const float4*)(hw + (size_t)s * H))[q];
    float* out = agg + (size_t)d * H + q * 4;
    atomicAdd(out + 0, norm * v.x);
    atomicAdd(out + 1, norm * v.y);
    atomicAdd(out + 2, norm * v.z);
    atomicAdd(out + 3, norm * v.w);
}

__global__ void k_bias_relu(const float* __restrict__ in, const float* __restrict__ b,
                            float* __restrict__ out, int H) {
    int i = blockIdx.x * blockDim.x + threadIdx.x;
    if (i >= NN * H) return;
    int c = i % H;
    out[i] = fmaxf(in[i] + b[c], 0.0f);
}

// -------------------------------- SGEMM --------------------------------------
// C[M,N] = A[M,K] @ B[K,N] (+bias)(+relu), all row-major.
// Dual-B: column tiles with col0 >= nsplit read from B2 at col0-nsplit.
// Tiles: BM=128, BN=128, BK=8; 256 threads; 8x8 micro-tile; double-buffered smem
// with register-staged global prefetch.
__global__ void __launch_bounds__(256, 2)
sgemm(int M, int N, int K,
      const float* __restrict__ A, int lda,
      const float* __restrict__ B, int ldb,
      const float* __restrict__ B2, int nsplit,
      float* __restrict__ C, int ldc,
      const float* __restrict__ bias, int do_relu)
{
    const int BK = 8;
    __shared__ float As[2][BK][128];
    __shared__ float Bs[2][BK][128];

    int tid = threadIdx.x;
    int tx = tid & 15;   // 16 col-groups * 8 cols
    int ty = tid >> 4;   // 16 row-groups * 8 rows
    int row0 = blockIdx.y * 128;
    int col0 = blockIdx.x * 128;

    const float* Bp = B;
    int cb = col0;
    if (col0 >= nsplit) { Bp = B2; cb = col0 - nsplit; }

    // A-tile loader: 128x8 floats = 256 float4, one per thread (transposed store)
    int am = tid >> 1;          // 0..127
    int ak = (tid & 1) << 2;    // 0 or 4
    // B-tile loader: 8x128 floats = 256 float4, one per thread
    int bk = tid >> 5;          // 0..7
    int bn = (tid & 31) << 2;   // 0..124

    const float* Aptr = A + (size_t)(row0 + am) * lda + ak;
    const float* Bptr = Bp + (size_t)bk * ldb + cb + bn;
    size_t bstep = (size_t)BK * ldb;

    // prologue: tile 0 -> buffer 0
    float4 av = *(const float4*)Aptr;
    float4 bv = *(const float4*)Bptr;
    As[0][ak + 0][am] = av.x;
    As[0][ak + 1][am] = av.y;
    As[0][ak + 2][am] = av.z;
    As[0][ak + 3][am] = av.w;
    *(float4*)&Bs[0][bk][bn] = bv;
    __syncthreads();

    float acc[8][8];
    #pragma unroll
    for (int i = 0; i < 8; i++)
        #pragma unroll
        for (int j = 0; j < 8; j++) acc[i][j] = 0.0f;

    int ntiles = K / BK;
    for (int t = 0; t < ntiles; t++) {
        int buf = t & 1;
        if (t + 1 < ntiles) {
            av = *(const float4*)(Aptr + (size_t)(t + 1) * BK);
            bv = *(const float4*)(Bptr + (size_t)(t + 1) * bstep);
        }
        #pragma unroll
        for (int k = 0; k < BK; k++) {
            float a[8], b[8];
            *(float4*)&a[0] = *(float4*)&As[buf][k][ty * 8];
            *(float4*)&a[4] = *(float4*)&As[buf][k][ty * 8 + 4];
            *(float4*)&b[0] = *(float4*)&Bs[buf][k][tx * 8];
            *(float4*)&b[4] = *(float4*)&Bs[buf][k][tx * 8 + 4];
            #pragma unroll
            for (int i = 0; i < 8; i++)
                #pragma unroll
                for (int j = 0; j < 8; j++)
                    acc[i][j] = fmaf(a[i], b[j], acc[i][j]);
        }
        if (t + 1 < ntiles) {
            int nb = buf ^ 1;
            As[nb][ak + 0][am] = av.x;
            As[nb][ak + 1][am] = av.y;
            As[nb][ak + 2][am] = av.z;
            As[nb][ak + 3][am] = av.w;
            *(float4*)&Bs[nb][bk][bn] = bv;
            __syncthreads();
        }
    }

    #pragma unroll
    for (int i = 0; i < 8; i++) {
        int gm = row0 + ty * 8 + i;
        #pragma unroll
        for (int j = 0; j < 8; j += 4) {
            int gn = col0 + tx * 8 + j;
            float4 v;
            v.x = acc[i][j + 0];
            v.y = acc[i][j + 1];
            v.z = acc[i][j + 2];
            v.w = acc[i][j + 3];
            if (bias) {
                v.x += bias[gn + 0];
                v.y += bias[gn + 1];
                v.z += bias[gn + 2];
                v.w += bias[gn + 3];
            }
            if (do_relu) {
                v.x = fmaxf(v.x, 0.0f);
                v.y = fmaxf(v.y, 0.0f);
                v.z = fmaxf(v.z, 0.0f);
                v.w = fmaxf(v.w, 0.0f);
            }
            *(float4*)&C[(size_t)gm * ldc + gn] = v;
        }
    }
}

// ------------------------------ host orchestration ---------------------------
static void launch_gemm(int M, int N, int K,
                        const float* A, int lda,
                        const float* B, int ldb,
                        const float* B2, int nsplit,
                        float* C, int ldc,
                        const float* bias, int do_relu)
{
    dim3 grid(N / 128, M / 128);
    sgemm<<<grid, 256>>>(M, N, K, A, lda, B, ldb, B2, nsplit, C, ldc, bias, do_relu);
}

extern "C" void kernel_launch(void* const* d_in, const int* in_sizes, int n_in,
                              void* d_out, int out_size)
{
    const float* x       = (const float*)d_in[0];
    const int*   eidx    = (const int*)  d_in[1];
    const float* sage_Wl = (const float*)d_in[2];
    const float* sage_bl = (const float*)d_in[3];
    const float* sage_Wr = (const float*)d_in[4];
    const float* gcn1_W  = (const float*)d_in[5];
    const float* gcn1_b  = (const float*)d_in[6];
    const float* gcn2_W  = (const float*)d_in[7];
    const float* gcn2_b  = (const float*)d_in[8];
    const float* fc1_W   = (const float*)d_in[9];
    const float* fc1_b   = (const float*)d_in[10];
    const float* fc2_W   = (const float*)d_in[11];
    const float* fc2_b   = (const float*)d_in[12];
    const float* out_W   = (const float*)d_in[13];
    const float* out_b   = (const float*)d_in[14];
    float* out = (float*)d_out;

    const int* src = eidx;        // edge_index[0]
    const int* dst = eidx + EE;   // edge_index[1]

    float *P, *A, *B, *C, *D, *E;
    cudaGetSymbolAddress((void**)&P, g_P);
    cudaGetSymbolAddress((void**)&A, g_A);
    cudaGetSymbolAddress((void**)&B, g_B);
    cudaGetSymbolAddress((void**)&C, g_C);
    cudaGetSymbolAddress((void**)&D, g_D);
    cudaGetSymbolAddress((void**)&E, g_E);

    const int TPB = 256;

    // degrees (shared by SAGE mean and both GCN layers)
    k_zero_cnt<<<(NN + TPB - 1) / TPB, TPB>>>();
    k_count<<<(EE + TPB - 1) / TPB, TPB>>>(dst);
    k_dinv<<<(NN + TPB - 1) / TPB, TPB>>>();

    // P = x @ [Wl | Wr]   (4096 x 4096 x 512)
    launch_gemm(NN, 512, NN, x, NN, sage_Wl, 256, sage_Wr, 256, P, 512, nullptr, 0);

    // SAGE: mean-aggregate P_l over edges, combine with P_r + bias, relu -> g_B
    k_zero_f<<<(NN * 256 + TPB - 1) / TPB, TPB>>>(A, NN * 256);
    k_sage_agg<<<(EE * 64 + TPB - 1) / TPB, TPB>>>(src, dst);
    k_sage_combine<<<(NN * 256 + TPB - 1) / TPB, TPB>>>(sage_bl);

    // GCN1: hw = h1 @ W  (4096 x 256 x 256), agg with sym-norm + self loops
    launch_gemm(NN, 256, 256, B, 256, gcn1_W, 256, gcn1_W, 256, C, 256, nullptr, 0);
    k_gcn_init<<<(NN * 256 + TPB - 1) / TPB, TPB>>>(C, A, 256);
    k_gcn_agg<<<(EE * 64 + TPB - 1) / TPB, TPB>>>(src, dst, C, A, 64);
    k_bias_relu<<<(NN * 256 + TPB - 1) / TPB, TPB>>>(A, gcn1_b, B, 256);

    // GCN2: 256 -> 128
    launch_gemm(NN, 128, 256, B, 256, gcn2_W, 128, gcn2_W, 128, D, 128, nullptr, 0);
    k_gcn_init<<<(NN * 128 + TPB - 1) / TPB, TPB>>>(D, E, 128);
    k_gcn_agg<<<(EE * 32 + TPB - 1) / TPB, TPB>>>(src, dst, D, E, 32);
    k_bias_relu<<<(NN * 128 + TPB - 1) / TPB, TPB>>>(E, gcn2_b, D, 128);

    // fc1: D -> E, fc2: E -> C (reusing g_C low half)
    launch_gemm(NN, 128, 128, D, 128, fc1_W, 128, fc1_W, 128, E, 128, fc1_b, 1);
    launch_gemm(NN, 128, 128, E, 128, fc2_W, 128, fc2_W, 128, C, 128, fc2_b, 1);

    // output head: logits = h5 @ out_W + out_b  (4096 x 128 x 16384)
    launch_gemm(NN, 16384, 128, C, 128, out_W, 16384, out_W, 16384, out, 16384, out_b, 0);
}

// round 3
// speedup vs baseline: 2.3820x; 1.7063x over previous
#include <cuda_runtime.h>
#include <cuda_bf16.h>
#include <math.h>
#include <stdint.h>

#define NN 4096
#define EE 65536

// ------------------- scratch (static device globals; no allocs) -------------
__device__ float g_P[NN * 512];
__device__ float g_A[NN * 256];
__device__ float g_B[NN * 256];
__device__ float g_C[NN * 256];
__device__ float g_D[NN * 128];
__device__ float g_E[NN * 128];
__device__ int   g_cnt[NN];
__device__ float g_dinv[NN];

// ------------------------------- utility kernels ----------------------------
__global__ void k_zero_cnt() {
    int i = blockIdx.x * blockDim.x + threadIdx.x;
    if (i < NN) g_cnt[i] = 0;
}
__global__ void k_count(const int* __restrict__ dst) {
    int e = blockIdx.x * blockDim.x + threadIdx.x;
    if (e < EE) atomicAdd(&g_cnt[dst[e]], 1);
}
__global__ void k_dinv() {
    int i = blockIdx.x * blockDim.x + threadIdx.x;
    if (i < NN) g_dinv[i] = rsqrtf((float)(g_cnt[i] + 1));
}
__global__ void k_zero_f(float* __restrict__ p, int n) {
    int i = blockIdx.x * blockDim.x + threadIdx.x;
    if (i < n) p[i] = 0.0f;
}
__global__ void k_sage_agg(const int* __restrict__ src, const int* __restrict__ dst) {
    int t = blockIdx.x * blockDim.x + threadIdx.x;
    if (t >= EE * 64) return;
    int e = t >> 6;
    int q = t & 63;
    int s = src[e];
    int d = dst[e];
    float4 v = ((const float4*)(g_P + (size_t)s * 512))[q];
    float* out = g_A + (size_t)d * 256 + q * 4;
    atomicAdd(out + 0, v.x);
    atomicAdd(out + 1, v.y);
    atomicAdd(out + 2, v.z);
    atomicAdd(out + 3, v.w);
}
__global__ void k_sage_combine(const float* __restrict__ bl) {
    int i = blockIdx.x * blockDim.x + threadIdx.x;
    if (i >= NN * 256) return;
    int v = i >> 8;
    int c = i & 255;
    float inv = 1.0f / fmaxf((float)g_cnt[v], 1.0f);
    float val = g_A[i] * inv + bl[c] + g_P[(size_t)v * 512 + 256 + c];
    g_B[i] = fmaxf(val, 0.0f);
}
__global__ void k_gcn_init(const float* __restrict__ hw, float* __restrict__ agg, int H) {
    int i = blockIdx.x * blockDim.x + threadIdx.x;
    if (i >= NN * H) return;
    int v = i / H;
    float dv = g_dinv[v];
    agg[i] = dv * dv * hw[i];
}
__global__ void k_gcn_agg(const int* __restrict__ src, const int* __restrict__ dst,
                          const float* __restrict__ hw, float* __restrict__ agg, int Hq) {
    int t = blockIdx.x * blockDim.x + threadIdx.x;
    if (t >= EE * Hq) return;
    int e = t / Hq;
    int q = t - e * Hq;
    int s = src[e];
    int d = dst[e];
    float norm = g_dinv[s] * g_dinv[d];
    int H = Hq * 4;
    float4 v = ((const float4*)(hw + (size_t)s * H))[q];
    float* out = agg + (size_t)d * H + q * 4;
    atomicAdd(out + 0, norm * v.x);
    atomicAdd(out + 1, norm * v.y);
    atomicAdd(out + 2, norm * v.z);
    atomicAdd(out + 3, norm * v.w);
}
__global__ void k_bias_relu(const float* __restrict__ in, const float* __restrict__ b,
                            float* __restrict__ out, int H) {
    int i = blockIdx.x * blockDim.x + threadIdx.x;
    if (i >= NN * H) return;
    int c = i % H;
    out[i] = fmaxf(in[i] + b[c], 0.0f);
}

// ---------------------------- fp32 SIMT GEMM (small layers) -----------------
__global__ void __launch_bounds__(256, 2)
sgemm(int M, int N, int K,
      const float* __restrict__ A, int lda,
      const float* __restrict__ B, int ldb,
      const float* __restrict__ B2, int nsplit,
      float* __restrict__ C, int ldc,
      const float* __restrict__ bias, int do_relu)
{
    const int BK = 8;
    __shared__ float As[2][BK][128];
    __shared__ float Bs[2][BK][128];

    int tid = threadIdx.x;
    int tx = tid & 15;
    int ty = tid >> 4;
    int row0 = blockIdx.y * 128;
    int col0 = blockIdx.x * 128;

    const float* Bp = B;
    int cb = col0;
    if (col0 >= nsplit) { Bp = B2; cb = col0 - nsplit; }

    int am = tid >> 1;
    int ak = (tid & 1) << 2;
    int bk = tid >> 5;
    int bn = (tid & 31) << 2;

    const float* Aptr = A + (size_t)(row0 + am) * lda + ak;
    const float* Bptr = Bp + (size_t)bk * ldb + cb + bn;
    size_t bstep = (size_t)BK * ldb;

    float4 av = *(const float4*)Aptr;
    float4 bv = *(const float4*)Bptr;
    As[0][ak + 0][am] = av.x;
    As[0][ak + 1][am] = av.y;
    As[0][ak + 2][am] = av.z;
    As[0][ak + 3][am] = av.w;
    *(float4*)&Bs[0][bk][bn] = bv;
    __syncthreads();

    float acc[8][8];
    #pragma unroll
    for (int i = 0; i < 8; i++)
        #pragma unroll
        for (int j = 0; j < 8; j++) acc[i][j] = 0.0f;

    int ntiles = K / BK;
    for (int t = 0; t < ntiles; t++) {
        int buf = t & 1;
        if (t + 1 < ntiles) {
            av = *(const float4*)(Aptr + (size_t)(t + 1) * BK);
            bv = *(const float4*)(Bptr + (size_t)(t + 1) * bstep);
        }
        #pragma unroll
        for (int k = 0; k < BK; k++) {
            float a[8], b[8];
            *(float4*)&a[0] = *(float4*)&As[buf][k][ty * 8];
            *(float4*)&a[4] = *(float4*)&As[buf][k][ty * 8 + 4];
            *(float4*)&b[0] = *(float4*)&Bs[buf][k][tx * 8];
            *(float4*)&b[4] = *(float4*)&Bs[buf][k][tx * 8 + 4];
            #pragma unroll
            for (int i = 0; i < 8; i++)
                #pragma unroll
                for (int j = 0; j < 8; j++)
                    acc[i][j] = fmaf(a[i], b[j], acc[i][j]);
        }
        if (t + 1 < ntiles) {
            int nb = buf ^ 1;
            As[nb][ak + 0][am] = av.x;
            As[nb][ak + 1][am] = av.y;
            As[nb][ak + 2][am] = av.z;
            As[nb][ak + 3][am] = av.w;
            *(float4*)&Bs[nb][bk][bn] = bv;
            __syncthreads();
        }
    }

    #pragma unroll
    for (int i = 0; i < 8; i++) {
        int gm = row0 + ty * 8 + i;
        #pragma unroll
        for (int j = 0; j < 8; j += 4) {
            int gn = col0 + tx * 8 + j;
            float4 v;
            v.x = acc[i][j + 0];
            v.y = acc[i][j + 1];
            v.z = acc[i][j + 2];
            v.w = acc[i][j + 3];
            if (bias) {
                v.x += bias[gn + 0];
                v.y += bias[gn + 1];
                v.z += bias[gn + 2];
                v.w += bias[gn + 3];
            }
            if (do_relu) {
                v.x = fmaxf(v.x, 0.0f);
                v.y = fmaxf(v.y, 0.0f);
                v.z = fmaxf(v.z, 0.0f);
                v.w = fmaxf(v.w, 0.0f);
            }
            *(float4*)&C[(size_t)gm * ldc + gn] = v;
        }
    }
}

// ---------------------------- tf32 tensor-core GEMM -------------------------
// C[M,N] = A[M,K] @ B[K,N] (+bias), row-major, via mma.sync.m16n8k8.tf32.
// BM=128, BK=16, 256 threads (8 warps). Template: BN, warp tile WM x WN.
// smem XOR swizzle (col ^ 8*(k&3)) -> conflict-free fragment loads.

__device__ __forceinline__ uint32_t f2tf32(float f) {
    uint32_t r;
    asm("cvt.rna.tf32.f32 %0, %1;" : "=r"(r) : "f"(f));
    return r;
}

__device__ __forceinline__ void mma_tf32(float* c, const uint32_t* a, const uint32_t* b) {
    asm volatile(
        "mma.sync.aligned.m16n8k8.row.col.f32.tf32.tf32.f32 "
        "{%0,%1,%2,%3}, {%4,%5,%6,%7}, {%8,%9}, {%0,%1,%2,%3};"
        : "+f"(c[0]), "+f"(c[1]), "+f"(c[2]), "+f"(c[3])
        : "r"(a[0]), "r"(a[1]), "r"(a[2]), "r"(a[3]), "r"(b[0]), "r"(b[1]));
}

template<int BN, int WM, int WN>
__global__ void __launch_bounds__(256, 2)
gemm_tf32(int M, int N, int K,
          const float* __restrict__ A, int lda,
          const float* __restrict__ B, int ldb,
          const float* __restrict__ B2, int nsplit,
          float* __restrict__ C, int ldc,
          const float* __restrict__ bias)
{
    const int BK = 16;
    const int MFRAG = WM / 16;
    const int NFRAG = WN / 8;
    const int WARPS_N = BN / WN;
    const int NB4 = (BK * BN / 4) / 256;   // B float4 loads per thread (1 or 2)

    __shared__ float As[2][BK][128];
    __shared__ float Bs[2][BK][BN];

    int tid = threadIdx.x;
    int lane = tid & 31;
    int warp = tid >> 5;
    int warp_m = warp / WARPS_N;
    int warp_n = warp % WARPS_N;
    int qm = lane >> 2;   // 0..7
    int qk = lane & 3;    // 0..3

    int row0 = blockIdx.y * 128;
    int col0 = blockIdx.x * BN;

    const float* Bp = B;
    int cb = col0;
    if (col0 >= nsplit) { Bp = B2; cb = col0 - nsplit; }

    // A loader: 128x16 = 512 float4, 2 per thread (transposed + swizzled store)
    int ar[2], akc[2];
    #pragma unroll
    for (int l = 0; l < 2; l++) {
        int i = tid + l * 256;
        ar[l]  = i >> 2;
        akc[l] = (i & 3) << 2;
    }
    // B loader: BK x BN, NB4 float4 per thread (swizzled float4 store)
    int bkk[2], bnn[2];
    #pragma unroll
    for (int l = 0; l < NB4; l++) {
        int i = tid + l * 256;
        bkk[l] = i / (BN / 4);
        bnn[l] = (i % (BN / 4)) * 4;
    }

    float4 avp[2], bvp[2];

    // prologue: load tile 0
    #pragma unroll
    for (int l = 0; l < 2; l++)
        avp[l] = *(const float4*)&A[(size_t)(row0 + ar[l]) * lda + akc[l]];
    #pragma unroll
    for (int l = 0; l < NB4; l++)
        bvp[l] = *(const float4*)&Bp[(size_t)bkk[l] * ldb + cb + bnn[l]];

    #pragma unroll
    for (int l = 0; l < 2; l++) {
        float v[4] = {avp[l].x, avp[l].y, avp[l].z, avp[l].w};
        #pragma unroll
        for (int j = 0; j < 4; j++) {
            int k = akc[l] + j;
            As[0][k][ar[l] ^ (8 * (k & 3))] = __uint_as_float(f2tf32(v[j]));
        }
    }
    #pragma unroll
    for (int l = 0; l < NB4; l++) {
        int k = bkk[l];
        float4 w;
        w.x = __uint_as_float(f2tf32(bvp[l].x));
        w.y = __uint_as_float(f2tf32(bvp[l].y));
        w.z = __uint_as_float(f2tf32(bvp[l].z));
        w.w = __uint_as_float(f2tf32(bvp[l].w));
        *(float4*)&Bs[0][k][bnn[l] ^ (8 * (k & 3))] = w;
    }
    __syncthreads();

    float acc[MFRAG][NFRAG][4];
    #pragma unroll
    for (int mi = 0; mi < MFRAG; mi++)
        #pragma unroll
        for (int ni = 0; ni < NFRAG; ni++)
            #pragma unroll
            for (int j = 0; j < 4; j++) acc[mi][ni][j] = 0.0f;

    int ntiles = K / BK;
    for (int t = 0; t < ntiles; t++) {
        int buf = t & 1;
        if (t + 1 < ntiles) {
            #pragma unroll
            for (int l = 0; l < 2; l++)
                avp[l] = *(const float4*)&A[(size_t)(row0 + ar[l]) * lda + (t + 1) * BK + akc[l]];
            #pragma unroll
            for (int l = 0; l < NB4; l++)
                bvp[l] = *(const float4*)&Bp[(size_t)((t + 1) * BK + bkk[l]) * ldb + cb + bnn[l]];
        }

        #pragma unroll
        for (int s = 0; s < 2; s++) {
            int swz = 8 * qk;
            uint32_t afr[MFRAG][4];
            uint32_t bfr[NFRAG][2];
            #pragma unroll
            for (int mi = 0; mi < MFRAG; mi++) {
                int m0 = warp_m * WM + mi * 16;
                afr[mi][0] = __float_as_uint(As[buf][8 * s + qk    ][(m0 + qm)     ^ swz]);
                afr[mi][1] = __float_as_uint(As[buf][8 * s + qk    ][(m0 + 8 + qm) ^ swz]);
                afr[mi][2] = __float_as_uint(As[buf][8 * s + 4 + qk][(m0 + qm)     ^ swz]);
                afr[mi][3] = __float_as_uint(As[buf][8 * s + 4 + qk][(m0 + 8 + qm) ^ swz]);
            }
            #pragma unroll
            for (int ni = 0; ni < NFRAG; ni++) {
                int n0 = warp_n * WN + ni * 8;
                bfr[ni][0] = __float_as_uint(Bs[buf][8 * s + qk    ][(n0 + qm) ^ swz]);
                bfr[ni][1] = __float_as_uint(Bs[buf][8 * s + 4 + qk][(n0 + qm) ^ swz]);
            }
            #pragma unroll
            for (int mi = 0; mi < MFRAG; mi++)
                #pragma unroll
                for (int ni = 0; ni < NFRAG; ni++)
                    mma_tf32(acc[mi][ni], afr[mi], bfr[ni]);
        }

        if (t + 1 < ntiles) {
            int nb = buf ^ 1;
            #pragma unroll
            for (int l = 0; l < 2; l++) {
                float v[4] = {avp[l].x, avp[l].y, avp[l].z, avp[l].w};
                #pragma unroll
                for (int j = 0; j < 4; j++) {
                    int k = akc[l] + j;
                    As[nb][k][ar[l] ^ (8 * (k & 3))] = __uint_as_float(f2tf32(v[j]));
                }
            }
            #pragma unroll
            for (int l = 0; l < NB4; l++) {
                int k = bkk[l];
                float4 w;
                w.x = __uint_as_float(f2tf32(bvp[l].x));
                w.y = __uint_as_float(f2tf32(bvp[l].y));
                w.z = __uint_as_float(f2tf32(bvp[l].z));
                w.w = __uint_as_float(f2tf32(bvp[l].w));
                *(float4*)&Bs[nb][k][bnn[l] ^ (8 * (k & 3))] = w;
            }
            __syncthreads();
        }
    }

    // epilogue
    #pragma unroll
    for (int mi = 0; mi < MFRAG; mi++) {
        int r = row0 + warp_m * WM + mi * 16 + qm;
        #pragma unroll
        for (int ni = 0; ni < NFRAG; ni++) {
            int c = col0 + warp_n * WN + ni * 8 + 2 * qk;
            float2 v0 = make_float2(acc[mi][ni][0], acc[mi][ni][1]);
            float2 v1 = make_float2(acc[mi][ni][2], acc[mi][ni][3]);
            if (bias) {
                float2 bb = *(const float2*)&bias[c];
                v0.x += bb.x; v0.y += bb.y;
                v1.x += bb.x; v1.y += bb.y;
            }
            *(float2*)&C[(size_t)r * ldc + c] = v0;
            *(float2*)&C[(size_t)(r + 8) * ldc + c] = v1;
        }
    }
}

// ------------------------------ host orchestration ---------------------------
static void launch_gemm(int M, int N, int K,
                        const float* A, int lda,
                        const float* B, int ldb,
                        const float* B2, int nsplit,
                        float* C, int ldc,
                        const float* bias, int do_relu)
{
    dim3 grid(N / 128, M / 128);
    sgemm<<<grid, 256>>>(M, N, K, A, lda, B, ldb, B2, nsplit, C, ldc, bias, do_relu);
}

extern "C" void kernel_launch(void* const* d_in, const int* in_sizes, int n_in,
                              void* d_out, int out_size)
{
    const float* x       = (const float*)d_in[0];
    const int*   eidx    = (const int*)  d_in[1];
    const float* sage_Wl = (const float*)d_in[2];
    const float* sage_bl = (const float*)d_in[3];
    const float* sage_Wr = (const float*)d_in[4];
    const float* gcn1_W  = (const float*)d_in[5];
    const float* gcn1_b  = (const float*)d_in[6];
    const float* gcn2_W  = (const float*)d_in[7];
    const float* gcn2_b  = (const float*)d_in[8];
    const float* fc1_W   = (const float*)d_in[9];
    const float* fc1_b   = (const float*)d_in[10];
    const float* fc2_W   = (const float*)d_in[11];
    const float* fc2_b   = (const float*)d_in[12];
    const float* out_W   = (const float*)d_in[13];
    const float* out_b   = (const float*)d_in[14];
    float* out = (float*)d_out;

    const int* src = eidx;
    const int* dst = eidx + EE;

    float *P, *A, *B, *C, *D, *E;
    cudaGetSymbolAddress((void**)&P, g_P);
    cudaGetSymbolAddress((void**)&A, g_A);
    cudaGetSymbolAddress((void**)&B, g_B);
    cudaGetSymbolAddress((void**)&C, g_C);
    cudaGetSymbolAddress((void**)&D, g_D);
    cudaGetSymbolAddress((void**)&E, g_E);

    const int TPB = 256;

    k_zero_cnt<<<(NN + TPB - 1) / TPB, TPB>>>();
    k_count<<<(EE + TPB - 1) / TPB, TPB>>>(dst);
    k_dinv<<<(NN + TPB - 1) / TPB, TPB>>>();

    // P = x @ [Wl | Wr]  (4096 x 512 x 4096) -- tf32 tensor cores, BN=64 (grid 256)
    {
        dim3 grid(512 / 64, NN / 128);
        gemm_tf32<64, 32, 32><<<grid, 256>>>(NN, 512, NN, x, NN,
                                             sage_Wl, 256, sage_Wr, 256,
                                             P, 512, nullptr);
    }

    // SAGE
    k_zero_f<<<(NN * 256 + TPB - 1) / TPB, TPB>>>(A, NN * 256);
    k_sage_agg<<<(EE * 64 + TPB - 1) / TPB, TPB>>>(src, dst);
    k_sage_combine<<<(NN * 256 + TPB - 1) / TPB, TPB>>>(sage_bl);

    // GCN1 (fp32 SIMT, small)
    launch_gemm(NN, 256, 256, B, 256, gcn1_W, 256, gcn1_W, 256, C, 256, nullptr, 0);
    k_gcn_init<<<(NN * 256 + TPB - 1) / TPB, TPB>>>(C, A, 256);
    k_gcn_agg<<<(EE * 64 + TPB - 1) / TPB, TPB>>>(src, dst, C, A, 64);
    k_bias_relu<<<(NN * 256 + TPB - 1) / TPB, TPB>>>(A, gcn1_b, B, 256);

    // GCN2
    launch_gemm(NN, 128, 256, B, 256, gcn2_W, 128, gcn2_W, 128, D, 128, nullptr, 0);
    k_gcn_init<<<(NN * 128 + TPB - 1) / TPB, TPB>>>(D, E, 128);
    k_gcn_agg<<<(EE * 32 + TPB - 1) / TPB, TPB>>>(src, dst, D, E, 32);
    k_bias_relu<<<(NN * 128 + TPB - 1) / TPB, TPB>>>(E, gcn2_b, D, 128);

    // fc1 / fc2
    launch_gemm(NN, 128, 128, D, 128, fc1_W, 128, fc1_W, 128, E, 128, fc1_b, 1);
    launch_gemm(NN, 128, 128, E, 128, fc2_W, 128, fc2_W, 128, C, 128, fc2_b, 1);

    // output head: 4096 x 16384 x 128 -- tf32 tensor cores, BN=128 (grid 4096)
    {
        dim3 grid(16384 / 128, NN / 128);
        gemm_tf32<128, 64, 32><<<grid, 256>>>(NN, 16384, 128, C, 128,
                                              out_W, 16384, out_W, 16384,
                                              out, 16384, out_b);
    }
}